// round 1
// baseline (speedup 1.0000x reference)
#include <cuda_runtime.h>

#define BB 16
#define SS 4096
#define CC 512
#define NTOT (BB*SS)
constexpr float A_COEF = 0.5f;

// Scratch (static device allocations — allowed; no cudaMalloc anywhere)
__device__ int   g_counts[BB*CC*CC];   // (b, target, argmax) joint histogram
__device__ float g_colsum[BB*CC];      // sum_s predicted[b,s,c]
__device__ float g_eqlse[BB*CC];       // sum_{s: t=c} lse[b,s]
__device__ float g_eqpred[BB*CC];      // sum_{s: t=c} predicted[b,s,m[b,c]]
__device__ float g_totlse[BB];         // sum_s lse[b,s]
__device__ int   g_m[BB*CC];
__device__ int   g_n[BB*CC];
__device__ int   g_tgt[NTOT];          // normalized int32 targets

// ---------------------------------------------------------------------------
// K_prep: zero scratch + normalize target dtype (int64 -> int32 if needed)
// ---------------------------------------------------------------------------
__global__ void k_prep(const void* __restrict__ tgt_raw) {
    const int tid = blockIdx.x * blockDim.x + threadIdx.x;
    const int nth = gridDim.x * blockDim.x;

    int4 z = make_int4(0, 0, 0, 0);
    int4* c4 = reinterpret_cast<int4*>(g_counts);
    const int n4 = (BB * CC * CC) / 4;
    for (int i = tid; i < n4; i += nth) c4[i] = z;

    for (int i = tid; i < BB * CC; i += nth) {
        g_colsum[i] = 0.f;
        g_eqlse[i]  = 0.f;
        g_eqpred[i] = 0.f;
    }
    if (tid < BB) g_totlse[tid] = 0.f;

    // dtype detection: if targets are int64, every u64 value is < 512.
    // If buffer is really int32, the high word of almost every "u64" is a
    // target in [0,512) (nonzero with prob 511/512) => value >= 2^32.
    const unsigned long long* t64 = (const unsigned long long*)tgt_raw;
    bool is64 = true;
#pragma unroll
    for (int k = 0; k < 16; k++)
        if (t64[k] >= (unsigned long long)CC) is64 = false;
    const int* t32 = (const int*)tgt_raw;
    for (int i = tid; i < NTOT; i += nth)
        g_tgt[i] = is64 ? (int)t64[i] : t32[i];
}

// ---------------------------------------------------------------------------
// K_main: per-row argmax + lse, histogram, lse sums, column sums.
// grid = (32, B), block = 512 (16 warps). One warp per row, 8 rows/warp.
// Lane l owns columns {4l..4l+3} + 128*j, j=0..3 (4x LDG.128, coalesced).
// ---------------------------------------------------------------------------
__global__ __launch_bounds__(512) void k_main(const float* __restrict__ pred) {
    __shared__ float s_col[CC];

    const int b    = blockIdx.y;
    const int warp = threadIdx.x >> 5;
    const int lane = threadIdx.x & 31;

    if (threadIdx.x < CC) s_col[threadIdx.x] = 0.f;
    __syncthreads();

    float csum[16];
#pragma unroll
    for (int i = 0; i < 16; i++) csum[i] = 0.f;
    float ltot = 0.f;

    const int s0 = blockIdx.x * 128 + warp * 8;
    for (int r = 0; r < 8; ++r) {
        const int s = s0 + r;
        const float4* row =
            reinterpret_cast<const float4*>(pred + ((size_t)b * SS + s) * CC);
        float4 v[4];
#pragma unroll
        for (int j = 0; j < 4; j++) v[j] = __ldg(&row[lane + 32 * j]);

        // local max/argmax (cols ascend within lane -> '>' keeps first max)
        float m = v[0].x;
        int   a = 4 * lane;
#pragma unroll
        for (int j = 0; j < 4; j++) {
            const float xs[4] = {v[j].x, v[j].y, v[j].z, v[j].w};
#pragma unroll
            for (int e = 0; e < 4; e++) {
                const int col = 4 * lane + 128 * j + e;
                const float x = xs[e];
                csum[j * 4 + e] += x;
                if (x > m) { m = x; a = col; }
            }
        }
        // warp argmax reduce: higher value wins; lower index on exact tie
#pragma unroll
        for (int off = 16; off > 0; off >>= 1) {
            float om = __shfl_xor_sync(0xffffffffu, m, off);
            int   oa = __shfl_xor_sync(0xffffffffu, a, off);
            if (om > m || (om == m && oa < a)) { m = om; a = oa; }
        }
        // expsum
        float sum = 0.f;
#pragma unroll
        for (int j = 0; j < 4; j++)
            sum += __expf(v[j].x - m) + __expf(v[j].y - m) +
                   __expf(v[j].z - m) + __expf(v[j].w - m);
#pragma unroll
        for (int off = 16; off > 0; off >>= 1)
            sum += __shfl_xor_sync(0xffffffffu, sum, off);
        const float lse = m + __logf(sum);
        ltot += lse;

        if (lane == 0) {
            const int t = g_tgt[b * SS + s];
            atomicAdd(&g_counts[(b * CC + t) * CC + a], 1);
            atomicAdd(&g_eqlse[b * CC + t], lse);
        }
    }
    if (lane == 0) atomicAdd(&g_totlse[b], ltot);

    // reduce column sums: smem atomics within block, then one global RED/col
#pragma unroll
    for (int j = 0; j < 4; j++)
#pragma unroll
        for (int e = 0; e < 4; e++)
            atomicAdd(&s_col[4 * lane + 128 * j + e], csum[j * 4 + e]);
    __syncthreads();
    if (threadIdx.x < CC)
        atomicAdd(&g_colsum[b * CC + threadIdx.x], s_col[threadIdx.x]);
}

// ---------------------------------------------------------------------------
// K_mode: one warp per (b, c): n = sum(counts row), m = argmax (first occ.)
// ---------------------------------------------------------------------------
__global__ __launch_bounds__(256) void k_mode() {
    const int wg   = (blockIdx.x * blockDim.x + threadIdx.x) >> 5;
    const int lane = threadIdx.x & 31;
    if (wg >= BB * CC) return;
    const int* row = &g_counts[(size_t)wg * CC];

    int n = 0, bc = -1, ba = CC;
#pragma unroll
    for (int j = 0; j < 16; j++) {
        const int col = lane + 32 * j;   // ascending per lane
        const int c = row[col];
        n += c;
        if (c > bc) { bc = c; ba = col; }
    }
#pragma unroll
    for (int off = 16; off > 0; off >>= 1) {
        int on = __shfl_xor_sync(0xffffffffu, n,  off);
        int oc = __shfl_xor_sync(0xffffffffu, bc, off);
        int oa = __shfl_xor_sync(0xffffffffu, ba, off);
        n += on;
        if (oc > bc || (oc == bc && oa < ba)) { bc = oc; ba = oa; }
    }
    if (lane == 0) { g_n[wg] = n; g_m[wg] = ba; }
}

// ---------------------------------------------------------------------------
// K_gather: one element per row: predicted[b, s, m[b, target[b,s]]]
// ---------------------------------------------------------------------------
__global__ void k_gather(const float* __restrict__ pred) {
    const int i = blockIdx.x * blockDim.x + threadIdx.x;
    if (i >= NTOT) return;
    const int b = i >> 12;  // / SS
    const int t = g_tgt[i];
    const int col = g_m[b * CC + t];
    const float v = pred[(size_t)i * CC + col];
    atomicAdd(&g_eqpred[b * CC + t], v);
}

// ---------------------------------------------------------------------------
// K_final: epilogue over 8192 (b, c) entries -> scalar
// ---------------------------------------------------------------------------
__global__ __launch_bounds__(256) void k_final(float* __restrict__ out) {
    __shared__ float s_tot[256];
    __shared__ int   s_cnt[256];
    float tot = 0.f;
    int   cnt = 0;
    for (int idx = threadIdx.x; idx < BB * CC; idx += 256) {
        const int b = idx >> 9;
        const int n = g_n[idx];
        const int m = g_m[idx];
        const float eq_sum  = g_eqlse[idx] - g_eqpred[idx];
        const float tterm   = g_totlse[b] - g_colsum[b * CC + m];
        const float ne_sum  = tterm - eq_sum;
        const float eq_loss = eq_sum / fmaxf((float)n, 1.f);
        const float ne_mean = ne_sum / fmaxf((float)(SS - n), 1.f);
        const bool present = (n > 0);
        const float denom = (present && ne_mean != 0.f) ? ne_mean : 1.f;
        const float val = eq_loss * (1.f - A_COEF) + A_COEF * (1.f / denom);
        const bool keep = present && (val != 0.f);
        if (keep) { tot += val; cnt += 1; }
    }
    s_tot[threadIdx.x] = tot;
    s_cnt[threadIdx.x] = cnt;
    __syncthreads();
    for (int off = 128; off > 0; off >>= 1) {
        if (threadIdx.x < off) {
            s_tot[threadIdx.x] += s_tot[threadIdx.x + off];
            s_cnt[threadIdx.x] += s_cnt[threadIdx.x + off];
        }
        __syncthreads();
    }
    if (threadIdx.x == 0) {
        int c = s_cnt[0] > 1 ? s_cnt[0] : 1;
        out[0] = s_tot[0] / (float)c;
    }
}

// ---------------------------------------------------------------------------
extern "C" void kernel_launch(void* const* d_in, const int* in_sizes, int n_in,
                              void* d_out, int out_size) {
    // metadata order should be (predicted, target); be robust to a swap
    const float* pred;
    const void*  tgt;
    if (in_sizes[0] == NTOT) { tgt = d_in[0]; pred = (const float*)d_in[1]; }
    else                     { pred = (const float*)d_in[0]; tgt = d_in[1]; }

    k_prep<<<2048, 256>>>(tgt);
    dim3 g1(32, BB);
    k_main<<<g1, 512>>>(pred);
    k_mode<<<(BB * CC * 32) / 256, 256>>>();
    k_gather<<<NTOT / 256, 256>>>(pred);
    k_final<<<1, 256>>>((float*)d_out);
}